// round 4
// baseline (speedup 1.0000x reference)
#include <cuda_runtime.h>

// ExodusNet: per-timestep dense (32 -> 1), ExpLeak scan, LIF scan with
// SingleSpike + MembraneSubtract.  x: (B, 32, 100) fp32 (t innermost),
// w: (32) fp32, out: (B, 100) fp32 of 0/1 spikes.
//
// R4: same compute structure as the 73.8us R3 kernel (float4 phase-1 loads,
// sequential f chain -> bitwise-stable numerics).  Changes:
//   - BPB 64 -> 32: grid 1024 (~6.9 blocks/SM) -> smaller last-wave tail,
//     more resident warps issuing LDGs.
//   - __ldcs / __stcs streaming hints: x and out have zero reuse; keep them
//     from churning L2.

namespace {

constexpr int T_STEPS    = 100;
constexpr int F_DIM      = 32;
constexpr int ROW_FLOATS = F_DIM * T_STEPS;       // 3200 floats per batch row
constexpr int BPB        = 32;                    // batch elements per block
constexpr int THREADS    = 256;                   // 8 warps
constexpr int B_PER_WARP = BPB / (THREADS / 32);  // 4
constexpr int SM_STRIDE  = 101;                   // conflict-free phase-2 reads

__device__ __forceinline__ float alpha_f() { return (float)0.9048374180359595; }
__device__ __forceinline__ float one_m_a() { return (float)(1.0 - 0.9048374180359595); }

__global__ __launch_bounds__(THREADS)
void exodus_kernel(const float* __restrict__ x,
                   const float* __restrict__ w,
                   float* __restrict__ out,
                   int B)
{
    __shared__ float wsh[F_DIM];
    extern __shared__ float ish[];                // BPB * SM_STRIDE floats

    const int tid  = threadIdx.x;
    const int warp = tid >> 5;
    const int lane = tid & 31;
    const int b0   = blockIdx.x * BPB;

    if (tid < F_DIM) wsh[tid] = w[tid];
    __syncthreads();

    // ---------------- Phase 1: weighted input currents i[b][t] ----------------
    // Warp-per-b; lanes 0..24 each own 4 consecutive timesteps (float4).
    // Per (b, f): one coalesced LDG.128.E.CS across 25 lanes (streaming,
    // evict-first -- x is read exactly once).
    {
        const int bl_begin = warp * B_PER_WARP;
        for (int bl = bl_begin; bl < bl_begin + B_PER_WARP; ++bl) {
            const int b = b0 + bl;
            if (b >= B) break;
            if (lane < 25) {
                const float* base = x + (size_t)b * ROW_FLOATS + 4 * lane;
                float4 acc = make_float4(0.f, 0.f, 0.f, 0.f);
                #pragma unroll
                for (int f = 0; f < F_DIM; ++f) {
                    const float4 xa =
                        __ldcs(reinterpret_cast<const float4*>(base + f * T_STEPS));
                    const float wf = wsh[f];
                    acc.x = fmaf(xa.x, wf, acc.x);
                    acc.y = fmaf(xa.y, wf, acc.y);
                    acc.z = fmaf(xa.z, wf, acc.z);
                    acc.w = fmaf(xa.w, wf, acc.w);
                }
                float* ip = ish + bl * SM_STRIDE + 4 * lane;
                ip[0] = acc.x;
                ip[1] = acc.y;
                ip[2] = acc.z;
                ip[3] = acc.w;
            }
        }
    }
    __syncthreads();

    // ---------------- Phase 2: sequential scans, one thread per b --------------
    // syn[t] = a*syn[t-1] + i[t]
    // v[t]   = a*v[t-1] + (1-a)*syn[t];  s = (v >= 1);  v -= s
    if (tid < BPB && (b0 + tid) < B) {
        float* ip = ish + tid * SM_STRIDE;
        float syn = 0.f, v = 0.f;
        #pragma unroll 4
        for (int t = 0; t < T_STEPS; ++t) {
            const float i = ip[t];
            syn = fmaf(alpha_f(), syn, i);
            v   = fmaf(alpha_f(), v, one_m_a() * syn);
            const float s = (v >= 1.0f) ? 1.0f : 0.0f;
            v -= s;
            ip[t] = s;
        }
    }
    __syncthreads();

    // ---------------- Phase 3: coalesced spike write-out (streaming) -----------
    {
        const int bl_begin = warp * B_PER_WARP;
        for (int bl = bl_begin; bl < bl_begin + B_PER_WARP; ++bl) {
            const int b = b0 + bl;
            if (b >= B) break;
            float* op       = out + (size_t)b * T_STEPS;
            const float* ip = ish + bl * SM_STRIDE;
            #pragma unroll
            for (int j = 0; j < 4; ++j) {
                const int t = lane + 32 * j;
                if (t < T_STEPS) __stcs(op + t, ip[t]);
            }
        }
    }
}

} // namespace

extern "C" void kernel_launch(void* const* d_in, const int* in_sizes, int n_in,
                              void* d_out, int out_size)
{
    const float* x = (const float*)d_in[0];
    const float* w = (const float*)d_in[1];
    float* out     = (float*)d_out;

    const int B = in_sizes[0] / ROW_FLOATS;   // 32768

    const int smem_bytes = BPB * SM_STRIDE * (int)sizeof(float);  // 12928
    cudaFuncSetAttribute(exodus_kernel,
                         cudaFuncAttributeMaxDynamicSharedMemorySize, smem_bytes);

    const int grid = (B + BPB - 1) / BPB;
    exodus_kernel<<<grid, THREADS, smem_bytes>>>(x, w, out, B);
}

// round 5
// speedup vs baseline: 1.0816x; 1.0816x over previous
#include <cuda_runtime.h>

// ExodusNet: per-timestep dense (32 -> 1), ExpLeak scan, LIF scan with
// SingleSpike + MembraneSubtract.  x: (B, 32, 100) fp32 (t innermost),
// w: (32) fp32, out: (B, 100) fp32 of 0/1 spikes.
//
// R5: phase-1 per-warp code is byte-identical to the 73.8us R3 kernel
// (float4 loads, B_PER_WARP=8, sequential f chain, no cache hints -- the
// codegen that gives regs=64 and ~10 LDG.128 in flight per warp).
// Only the launch shape changes: THREADS 256 -> 128, BPB 64 -> 32.
//   regs 64 x 128thr = 8K/block -> 8 blocks/SM (RF-capped) -> capacity
//   148*8 = 1184 >= grid 1024 -> single wave with 7-vs-6 block imbalance
//   (~1.4% tail) instead of R3's 4-vs-3 (~15% tail).  Warps/SM unchanged.

namespace {

constexpr int T_STEPS    = 100;
constexpr int F_DIM      = 32;
constexpr int ROW_FLOATS = F_DIM * T_STEPS;       // 3200 floats per batch row
constexpr int BPB        = 32;                    // batch elements per block
constexpr int THREADS    = 128;                   // 4 warps
constexpr int B_PER_WARP = BPB / (THREADS / 32);  // 8 (same as R3)
constexpr int SM_STRIDE  = 101;                   // conflict-free phase-2 reads

__device__ __forceinline__ float alpha_f() { return (float)0.9048374180359595; }
__device__ __forceinline__ float one_m_a() { return (float)(1.0 - 0.9048374180359595); }

__global__ __launch_bounds__(THREADS)
void exodus_kernel(const float* __restrict__ x,
                   const float* __restrict__ w,
                   float* __restrict__ out,
                   int B)
{
    __shared__ float wsh[F_DIM];
    extern __shared__ float ish[];                // BPB * SM_STRIDE floats

    const int tid  = threadIdx.x;
    const int warp = tid >> 5;
    const int lane = tid & 31;
    const int b0   = blockIdx.x * BPB;

    if (tid < F_DIM) wsh[tid] = w[tid];
    __syncthreads();

    // ---------------- Phase 1: weighted input currents i[b][t] ----------------
    // Warp-per-b; lanes 0..24 each own 4 consecutive timesteps (float4).
    // Per (b, f): one coalesced LDG.128 across 25 lanes.  float4 destinations
    // force ptxas to batch the loads (4 chain inputs per scoreboard slot).
    {
        const int bl_begin = warp * B_PER_WARP;
        for (int bl = bl_begin; bl < bl_begin + B_PER_WARP; ++bl) {
            const int b = b0 + bl;
            if (b >= B) break;
            if (lane < 25) {
                const float* base = x + (size_t)b * ROW_FLOATS + 4 * lane;
                float4 acc = make_float4(0.f, 0.f, 0.f, 0.f);
                #pragma unroll
                for (int f = 0; f < F_DIM; ++f) {
                    const float4 xa = *reinterpret_cast<const float4*>(base + f * T_STEPS);
                    const float wf = wsh[f];
                    acc.x = fmaf(xa.x, wf, acc.x);
                    acc.y = fmaf(xa.y, wf, acc.y);
                    acc.z = fmaf(xa.z, wf, acc.z);
                    acc.w = fmaf(xa.w, wf, acc.w);
                }
                float* ip = ish + bl * SM_STRIDE + 4 * lane;
                ip[0] = acc.x;
                ip[1] = acc.y;
                ip[2] = acc.z;
                ip[3] = acc.w;
            }
        }
    }
    __syncthreads();

    // ---------------- Phase 2: sequential scans, one thread per b --------------
    // syn[t] = a*syn[t-1] + i[t]
    // v[t]   = a*v[t-1] + (1-a)*syn[t];  s = (v >= 1);  v -= s
    // Bank for (tid, t): (5*tid + t) % 32 -- conflict-free across tid.
    if (tid < BPB && (b0 + tid) < B) {
        float* ip = ish + tid * SM_STRIDE;
        float syn = 0.f, v = 0.f;
        #pragma unroll 4
        for (int t = 0; t < T_STEPS; ++t) {
            const float i = ip[t];
            syn = fmaf(alpha_f(), syn, i);
            v   = fmaf(alpha_f(), v, one_m_a() * syn);
            const float s = (v >= 1.0f) ? 1.0f : 0.0f;
            v -= s;
            ip[t] = s;
        }
    }
    __syncthreads();

    // ---------------- Phase 3: coalesced spike write-out -----------------------
    {
        const int bl_begin = warp * B_PER_WARP;
        for (int bl = bl_begin; bl < bl_begin + B_PER_WARP; ++bl) {
            const int b = b0 + bl;
            if (b >= B) break;
            float* op       = out + (size_t)b * T_STEPS;
            const float* ip = ish + bl * SM_STRIDE;
            #pragma unroll
            for (int j = 0; j < 4; ++j) {
                const int t = lane + 32 * j;
                if (t < T_STEPS) op[t] = ip[t];
            }
        }
    }
}

} // namespace

extern "C" void kernel_launch(void* const* d_in, const int* in_sizes, int n_in,
                              void* d_out, int out_size)
{
    const float* x = (const float*)d_in[0];
    const float* w = (const float*)d_in[1];
    float* out     = (float*)d_out;

    const int B = in_sizes[0] / ROW_FLOATS;   // 32768

    const int smem_bytes = BPB * SM_STRIDE * (int)sizeof(float);  // 12928
    cudaFuncSetAttribute(exodus_kernel,
                         cudaFuncAttributeMaxDynamicSharedMemorySize, smem_bytes);

    const int grid = (B + BPB - 1) / BPB;   // 1024
    exodus_kernel<<<grid, THREADS, smem_bytes>>>(x, w, out, B);
}

// round 6
// speedup vs baseline: 1.1364x; 1.0506x over previous
#include <cuda_runtime.h>
#include <cstdint>

// ExodusNet: per-timestep dense (32 -> 1), ExpLeak scan, LIF scan with
// SingleSpike + MembraneSubtract.  x: (B, 32, 100) fp32 (t innermost),
// w: (32) fp32, out: (B, 100) fp32 of 0/1 spikes.
//
// R6: replace the LDG phase-1 path (plateaued at 5.9 TB/s, RF-bound) with
// cp.async.bulk (UBLKCP) streaming: each warp owns 4 batch rows; one 12800B
// contiguous bulk copy per row into a private 2-stage SMEM ring, mbarrier
// expect_tx/parity sync.  FMA chain / scan / writeout orderings are bitwise
// identical to the rel_err==0 kernels.

namespace {

constexpr int T_STEPS    = 100;
constexpr int F_DIM      = 32;
constexpr int ROW_FLOATS = F_DIM * T_STEPS;        // 3200 floats per row
constexpr int CHUNK      = ROW_FLOATS * 4;         // 12800 bytes per row
constexpr int THREADS    = 128;                    // 4 warps
constexpr int BPB        = 16;                     // batch rows per block
constexpr int B_PER_WARP = BPB / (THREADS / 32);   // 4
constexpr int NSTAGE     = 2;                      // ring depth per warp
constexpr int SM_STRIDE  = 101;                    // conflict-free scan reads

// dynamic smem layout (bytes)
constexpr int WSH_OFF  = 0;                        // 32 floats
constexpr int MBAR_OFF = 128;                      // 4 warps * 2 stages * 8B
constexpr int ISH_OFF  = 192;                      // BPB * SM_STRIDE floats
constexpr int RING_OFF = ISH_OFF + BPB * SM_STRIDE * 4 + (16 - (BPB * SM_STRIDE * 4) % 16) % 16;
constexpr int SMEM_BYTES = RING_OFF + 4 * NSTAGE * CHUNK;   // ~109 KB

__device__ __forceinline__ float alpha_f() { return (float)0.9048374180359595; }
__device__ __forceinline__ float one_m_a() { return (float)(1.0 - 0.9048374180359595); }

__device__ __forceinline__ uint32_t smem_u32(const void* p) {
    uint32_t a;
    asm("{ .reg .u64 t; cvta.to.shared.u64 t, %1; cvt.u32.u64 %0, t; }"
        : "=r"(a) : "l"(p));
    return a;
}

__device__ __forceinline__ void mbar_init(uint32_t mbar, uint32_t cnt) {
    asm volatile("mbarrier.init.shared.b64 [%0], %1;" :: "r"(mbar), "r"(cnt) : "memory");
}
__device__ __forceinline__ void mbar_expect_tx(uint32_t mbar, uint32_t bytes) {
    asm volatile("mbarrier.arrive.expect_tx.shared.b64 _, [%0], %1;"
                 :: "r"(mbar), "r"(bytes) : "memory");
}
__device__ __forceinline__ void bulk_copy_g2s(uint32_t dst_smem, const void* src_gmem,
                                              uint32_t bytes, uint32_t mbar) {
    asm volatile(
        "cp.async.bulk.shared::cluster.global.mbarrier::complete_tx::bytes "
        "[%0], [%1], %2, [%3];"
        :: "r"(dst_smem), "l"(src_gmem), "r"(bytes), "r"(mbar) : "memory");
}
__device__ __forceinline__ void mbar_wait_parity(uint32_t mbar, uint32_t parity) {
    asm volatile(
        "{\n\t"
        ".reg .pred P1;\n\t"
        "WAIT_LOOP_%=:\n\t"
        "mbarrier.try_wait.parity.acquire.cta.shared::cta.b64 P1, [%0], %1, 0x989680;\n\t"
        "@P1 bra.uni WAIT_DONE_%=;\n\t"
        "bra.uni WAIT_LOOP_%=;\n\t"
        "WAIT_DONE_%=:\n\t"
        "}"
        :: "r"(mbar), "r"(parity) : "memory");
}

__global__ __launch_bounds__(THREADS)
void exodus_kernel(const float* __restrict__ x,
                   const float* __restrict__ w,
                   float* __restrict__ out,
                   int B)
{
    extern __shared__ __align__(16) unsigned char smem_raw[];
    float* wsh = reinterpret_cast<float*>(smem_raw + WSH_OFF);
    float* ish = reinterpret_cast<float*>(smem_raw + ISH_OFF);

    const uint32_t smem_base = smem_u32(smem_raw);
    const int tid  = threadIdx.x;
    const int warp = tid >> 5;
    const int lane = tid & 31;
    const int b0   = blockIdx.x * BPB;

    if (tid < F_DIM) wsh[tid] = w[tid];
    if (tid == 0) {
        #pragma unroll
        for (int m = 0; m < 4 * NSTAGE; ++m)
            mbar_init(smem_base + MBAR_OFF + m * 8, 1);
    }
    __syncthreads();

    // ---------------- Phase 1: TMA-streamed weighted currents ------------------
    const int      wb_base   = b0 + warp * B_PER_WARP;          // warp's first b
    const uint32_t ring_base = smem_base + RING_OFF + warp * (NSTAGE * CHUNK);
    const uint32_t mbar_base = smem_base + MBAR_OFF + warp * (NSTAGE * 8);

    // prologue: fill both stages
    if (lane == 0) {
        #pragma unroll
        for (int s = 0; s < NSTAGE; ++s) {
            const int b = wb_base + s;
            if (b < B) {
                mbar_expect_tx(mbar_base + s * 8, CHUNK);
                bulk_copy_g2s(ring_base + s * CHUNK, x + (size_t)b * ROW_FLOATS,
                              CHUNK, mbar_base + s * 8);
            }
        }
    }

    #pragma unroll
    for (int i = 0; i < B_PER_WARP; ++i) {
        const int b = wb_base + i;
        if (b >= B) break;
        const int s  = i & 1;
        const int ph = (i >> 1) & 1;
        mbar_wait_parity(mbar_base + s * 8, (uint32_t)ph);

        if (lane < 25) {
            const float* stage =
                reinterpret_cast<const float*>(smem_raw + RING_OFF +
                                               warp * (NSTAGE * CHUNK) + s * CHUNK);
            const float* base = stage + 4 * lane;
            float4 acc = make_float4(0.f, 0.f, 0.f, 0.f);
            #pragma unroll
            for (int f = 0; f < F_DIM; ++f) {
                const float4 xa = *reinterpret_cast<const float4*>(base + f * T_STEPS);
                const float wf = wsh[f];
                acc.x = fmaf(xa.x, wf, acc.x);
                acc.y = fmaf(xa.y, wf, acc.y);
                acc.z = fmaf(xa.z, wf, acc.z);
                acc.w = fmaf(xa.w, wf, acc.w);
            }
            float* ip = ish + (warp * B_PER_WARP + i) * SM_STRIDE + 4 * lane;
            ip[0] = acc.x;
            ip[1] = acc.y;
            ip[2] = acc.z;
            ip[3] = acc.w;
        }
        __syncwarp();   // all lanes done reading stage s before reissue

        const int nxt = i + NSTAGE;
        if (nxt < B_PER_WARP && lane == 0) {
            const int nb = wb_base + nxt;
            if (nb < B) {
                mbar_expect_tx(mbar_base + s * 8, CHUNK);
                bulk_copy_g2s(ring_base + s * CHUNK, x + (size_t)nb * ROW_FLOATS,
                              CHUNK, mbar_base + s * 8);
            }
        }
    }
    __syncthreads();

    // ---------------- Phase 2: sequential scans, one thread per b --------------
    if (tid < BPB && (b0 + tid) < B) {
        float* ip = ish + tid * SM_STRIDE;
        float syn = 0.f, v = 0.f;
        #pragma unroll 4
        for (int t = 0; t < T_STEPS; ++t) {
            const float i = ip[t];
            syn = fmaf(alpha_f(), syn, i);
            v   = fmaf(alpha_f(), v, one_m_a() * syn);
            const float s = (v >= 1.0f) ? 1.0f : 0.0f;
            v -= s;
            ip[t] = s;
        }
    }
    __syncthreads();

    // ---------------- Phase 3: coalesced spike write-out -----------------------
    {
        const int bl_begin = warp * B_PER_WARP;
        for (int bl = bl_begin; bl < bl_begin + B_PER_WARP; ++bl) {
            const int b = b0 + bl;
            if (b >= B) break;
            float* op       = out + (size_t)b * T_STEPS;
            const float* ip = ish + bl * SM_STRIDE;
            #pragma unroll
            for (int j = 0; j < 4; ++j) {
                const int t = lane + 32 * j;
                if (t < T_STEPS) op[t] = ip[t];
            }
        }
    }
}

} // namespace

extern "C" void kernel_launch(void* const* d_in, const int* in_sizes, int n_in,
                              void* d_out, int out_size)
{
    const float* x = (const float*)d_in[0];
    const float* w = (const float*)d_in[1];
    float* out     = (float*)d_out;

    const int B = in_sizes[0] / ROW_FLOATS;   // 32768

    cudaFuncSetAttribute(exodus_kernel,
                         cudaFuncAttributeMaxDynamicSharedMemorySize, SMEM_BYTES);

    const int grid = (B + BPB - 1) / BPB;     // 2048
    exodus_kernel<<<grid, THREADS, SMEM_BYTES>>>(x, w, out, B);
}